// round 13
// baseline (speedup 1.0000x reference)
#include <cuda_runtime.h>
#include <cuda_fp16.h>
#include <cstdint>

#define BB 16
#define CC 256
#define HH 128
#define WW 128
#define NV 4096
#define DD 256
#define MROWS (BB * NV)   // 65536
#define HWSZ (HH * WW)    // 16384
#define NTILES (MROWS / 64)   // 1024
#define NPROD 128

// ---------------- scratch (static __device__: allocation-free) ----------------
__device__ __half g_featT[(size_t)BB * HWSZ * CC];   // 128 MiB transposed features (B,HW,C) fp16
__device__ __half g_Wh[3][DD * CC];                  // weights [N,K] K-major, fp16
__device__ int g_flags[20];                          // [0..15]=batch counters, [16]=tile queue

__device__ __forceinline__ float read_img(const int* p) {
    int iv = *p;
    if (iv > 1 && iv < (1 << 24)) return (float)iv;
    return __int_as_float(iv);
}

// ---------------- family-agnostic PTX helpers (sm_80+) ----------------
__device__ __forceinline__ uint32_t smem_u32(const void* p) {
    uint32_t a;
    asm("{ .reg .u64 t; cvta.to.shared.u64 t, %1; cvt.u32.u64 %0, t; }" : "=r"(a) : "l"(p));
    return a;
}
__device__ __forceinline__ void cpa16(uint32_t dst, const void* src) {
    asm volatile("cp.async.cg.shared.global [%0], [%1], 16;" :: "r"(dst), "l"(src));
}
#define CP_COMMIT() asm volatile("cp.async.commit_group;" ::: "memory")
#define CP_WAIT2() asm volatile("cp.async.wait_group 2;" ::: "memory")
#define CP_WAIT1() asm volatile("cp.async.wait_group 1;" ::: "memory")
#define CP_WAIT0() asm volatile("cp.async.wait_group 0;" ::: "memory")

__device__ __forceinline__ void ldsm4(uint32_t a, uint32_t& r0, uint32_t& r1,
                                      uint32_t& r2, uint32_t& r3) {
    asm volatile("ldmatrix.sync.aligned.m8n8.x4.shared.b16 {%0,%1,%2,%3}, [%4];"
                 : "=r"(r0), "=r"(r1), "=r"(r2), "=r"(r3) : "r"(a));
}
__device__ __forceinline__ void mma16816(float* c, const uint32_t* a, const uint32_t* b) {
    asm volatile(
        "mma.sync.aligned.m16n8k16.row.col.f32.f16.f16.f32 "
        "{%0,%1,%2,%3}, {%4,%5,%6,%7}, {%8,%9}, {%0,%1,%2,%3};"
        : "+f"(c[0]), "+f"(c[1]), "+f"(c[2]), "+f"(c[3])
        : "r"(a[0]), "r"(a[1]), "r"(a[2]), "r"(a[3]), "r"(b[0]), "r"(b[1]));
}
__device__ __forceinline__ void sts32(uint32_t a, uint32_t v) {
    asm volatile("st.shared.b32 [%0], %1;" :: "r"(a), "r"(v));
}
__device__ __forceinline__ void sts128(uint32_t a, uint4 v) {
    asm volatile("st.shared.v4.b32 [%0], {%1,%2,%3,%4};"
                 :: "r"(a), "r"(v.x), "r"(v.y), "r"(v.z), "r"(v.w));
}

// ---------------------------------------------------------------------------
// K1: weight prep -> Wt[n*K+k] = W[k*Nd+n] as fp16
// ---------------------------------------------------------------------------
__global__ void prep_weights(const float* __restrict__ W1, const float* __restrict__ W2,
                             const float* __restrict__ Wp) {
    int idx = blockIdx.x * 256 + threadIdx.x;
    int w = blockIdx.y;
    const float* W = (w == 0) ? W1 : (w == 1) ? W2 : Wp;
    int n = idx >> 8, k = idx & 255;
    g_Wh[w][n * CC + k] = __float2half_rn(W[k * DD + n]);
}

// ---------------------------------------------------------------------------
// K2: PERSISTENT producer/consumer kernel.
//   grid = 2*SMs (ALL CTAs co-resident -> cross-CTA spin is safe).
//   bid < 128: transpose producers (2 hw-strips x 4 c-tiles per batch,
//   batches in order; per-batch counter -> ready flags), then join consumers.
//   Consumers pull 64-row tiles from an atomic queue; per tile: weight
//   prefetch -> spin on batch flag -> bilinear gather -> fused 3-layer MLP.
// ---------------------------------------------------------------------------
#define SMEM_A 32768
#define STAGE_B 16384
#define GSMEM (SMEM_A + 4 * STAGE_B)   // 98304 -> 2 CTAs/SM

__global__ void __launch_bounds__(256, 2)
mega_kernel(const float* __restrict__ features, const __half* __restrict__ Wh,
            const float* __restrict__ b1, const float* __restrict__ b2,
            const float* __restrict__ bp, float* __restrict__ OutF,
            const float* __restrict__ verts, const int* __restrict__ imgp) {
    extern __shared__ char smem[];
    const uint32_t sb = smem_u32(smem);
    const int tid = threadIdx.x;
    const int bid = blockIdx.x;
    const int warp = tid >> 5, lane = tid & 31;
    const int wm = warp >> 2, wn = warp & 3;   // 2m x 4n warps -> 32x64 tiles

    // ================= PRODUCER PHASE (bid < 128) =================
    if (bid < NPROD) {
        float* ft = (float*)smem;   // 4 tiles of 64x65 fp32 = 66560 B
        for (int b = 0; b < BB; b++) {
            const float* s = features + (size_t)b * CC * HWSZ;
            __half* d = g_featT + (size_t)b * HWSZ * CC;
#pragma unroll
            for (int ss = 0; ss < 2; ss++) {
                int hw0 = (bid + ss * NPROD) * 64;
#pragma unroll
                for (int t = 0; t < 4; t++)
#pragma unroll
                    for (int i = 0; i < 4; i++) {
                        int idx = tid + i * 256;
                        int r = idx >> 4, q = idx & 15;
                        float4 v = *(const float4*)(s + (size_t)(t * 64 + r) * HWSZ + hw0 + q * 4);
                        float* p = ft + t * 4160 + r * 65 + q * 4;
                        p[0] = v.x; p[1] = v.y; p[2] = v.z; p[3] = v.w;
                    }
                __syncthreads();
#pragma unroll
                for (int t = 0; t < 4; t++)
#pragma unroll
                    for (int i = 0; i < 2; i++) {
                        int idx = tid + i * 256;
                        int r = idx >> 3, q = idx & 7;
                        __half2 h[4];
#pragma unroll
                        for (int j = 0; j < 4; j++) {
                            float a = ft[t * 4160 + (q * 8 + 2 * j + 0) * 65 + r];
                            float c2 = ft[t * 4160 + (q * 8 + 2 * j + 1) * 65 + r];
                            h[j] = __floats2half2_rn(a, c2);
                        }
                        *(uint4*)(d + (size_t)(hw0 + r) * CC + t * 64 + q * 8) = *(uint4*)h;
                    }
                __syncthreads();
            }
            __threadfence();
            __syncthreads();
            if (tid == 0) atomicAdd(&g_flags[b], 1);
        }
    }

    // ================= CONSUMER PHASE (all CTAs) =================
    // ---- weight chunk loader: ci 0..23 -> phase ci>>3, K32 chunk ci&7 ----
    auto loadB = [&](int s, int ci) {
        int ph = ci >> 3;
        uint32_t cofs = (uint32_t)(ci & 7) << 5;
        const __half* wh = Wh + (size_t)ph * DD * CC;
        uint32_t dstb = sb + SMEM_A + (uint32_t)s * STAGE_B;
#pragma unroll
        for (int i = 0; i < 4; i++) {
            int idx = i * 256 + tid;
            int rb = idx >> 2;
            uint32_t u = (uint32_t)(idx & 3);
            uint32_t sw = (uint32_t)(rb << 6) + ((u ^ (uint32_t)((rb >> 1) & 3)) << 4);
            cpa16(dstb + sw, wh + (size_t)rb * CC + cofs + u * 8);
        }
    };

    // ---- ldsm offsets (tile-independent) ----
    uint32_t aOff[2], bOff[4];
#pragma unroll
    for (int mt = 0; mt < 2; mt++) {
        int r = wm * 32 + mt * 16 + (lane & 15);
        uint32_t kb = (uint32_t)(lane >> 4);
        aOff[mt] = (uint32_t)(r << 9) + ((kb ^ (uint32_t)(r & 7)) << 4);
    }
#pragma unroll
    for (int n2 = 0; n2 < 4; n2++) {
        int rb = wn * 64 + n2 * 16 + (lane & 7) + ((lane >> 4) << 3);
        uint32_t kb = (uint32_t)((lane >> 3) & 1);
        bOff[n2] = (uint32_t)(rb << 6) + ((kb ^ (uint32_t)((rb >> 1) & 3)) << 4);
    }
    const int rl0 = wm * 32 + (lane >> 2);
    const int cl0 = wn * 64 + (lane & 3) * 2;

    while (true) {
        // pull next tile from the queue (block-wide broadcast via smem)
        if (tid == 0) *(volatile int*)smem = atomicAdd(&g_flags[16], 1);
        __syncthreads();
        const int tile = *(volatile int*)smem;
        if (tile >= NTILES) break;
        const int brow = tile * 64;
        const int batch = tile >> 6;

        float acc[2][8][4];
#pragma unroll
        for (int i = 0; i < 2; i++)
#pragma unroll
            for (int j = 0; j < 8; j++)
#pragma unroll
                for (int q = 0; q < 4; q++) acc[i][j][q] = 0.0f;

        // prefetch weights (independent of feature readiness)
        loadB(0, 0);
        CP_COMMIT();
        loadB(1, 1);
        CP_COMMIT();
        loadB(2, 2);
        CP_COMMIT();

        // spin until this tile's batch is fully transposed
        if (tid == 0) {
            while (atomicAdd(&g_flags[batch], 0) < NPROD) __nanosleep(100);
            __threadfence();
        }
        __syncthreads();

        // ---- PROLOGUE: bilinear gather -> A smem (warp = 8 vertices) ----
        {
            float img = read_img(imgp);
            float denom = img - 1.0f;
            const __half* fbase = g_featT + (size_t)batch * HWSZ * CC;
#pragma unroll
            for (int i = 0; i < 8; i++) {
                int rl = warp * 8 + i;
                int v = brow + rl;
                float gx = 2.0f * verts[2 * v + 0] / denom - 1.0f;
                float gy = 2.0f * verts[2 * v + 1] / denom - 1.0f;
                float ix = (gx + 1.0f) * 0.5f * (float)(WW - 1);
                float iy = (gy + 1.0f) * 0.5f * (float)(HH - 1);
                ix = fminf(fmaxf(ix, 0.0f), (float)(WW - 1));
                iy = fminf(fmaxf(iy, 0.0f), (float)(HH - 1));
                float x0f = floorf(ix), y0f = floorf(iy);
                float wx = ix - x0f, wy = iy - y0f;
                int x0 = min(max((int)x0f, 0), WW - 1);
                int y0 = min(max((int)y0f, 0), HH - 1);
                int x1 = min(x0 + 1, WW - 1);
                int y1 = min(y0 + 1, HH - 1);

                const __half* p00 = fbase + (size_t)(y0 * WW + x0) * CC + lane * 8;
                const __half* p01 = fbase + (size_t)(y0 * WW + x1) * CC + lane * 8;
                const __half* p10 = fbase + (size_t)(y1 * WW + x0) * CC + lane * 8;
                const __half* p11 = fbase + (size_t)(y1 * WW + x1) * CC + lane * 8;
                uint4 u00 = *(const uint4*)p00;
                uint4 u01 = *(const uint4*)p01;
                uint4 u10 = *(const uint4*)p10;
                uint4 u11 = *(const uint4*)p11;

                float omx = 1.0f - wx, omy = 1.0f - wy;
                float w00 = omx * omy, w01 = wx * omy, w10 = omx * wy, w11 = wx * wy;
                const uint32_t* a00 = (const uint32_t*)&u00;
                const uint32_t* a01 = (const uint32_t*)&u01;
                const uint32_t* a10 = (const uint32_t*)&u10;
                const uint32_t* a11 = (const uint32_t*)&u11;
                uint4 ov;
                uint32_t* op = (uint32_t*)&ov;
#pragma unroll
                for (int t = 0; t < 4; t++) {
                    float2 f00 = __half22float2(*(const __half2*)&a00[t]);
                    float2 f01 = __half22float2(*(const __half2*)&a01[t]);
                    float2 f10 = __half22float2(*(const __half2*)&a10[t]);
                    float2 f11 = __half22float2(*(const __half2*)&a11[t]);
                    float r0 = f00.x * w00 + f01.x * w01 + f10.x * w10 + f11.x * w11;
                    float r1 = f00.y * w00 + f01.y * w01 + f10.y * w10 + f11.y * w11;
                    __half2 h2 = __floats2half2_rn(r0, r1);
                    op[t] = reinterpret_cast<uint32_t&>(h2);
                }
                sts128(sb + (uint32_t)(rl << 9) + (((uint32_t)lane ^ (uint32_t)(rl & 7)) << 4), ov);
            }
        }

        // ---- fused 3-phase MLP main loop ----
#pragma unroll
        for (int ph = 0; ph < 3; ph++) {
#pragma unroll
            for (int c = 0; c < 8; c++) {
                const int ci = ph * 8 + c;
                if (ci <= 21) CP_WAIT2();
                else if (ci == 22) CP_WAIT1();
                else CP_WAIT0();
                __syncthreads();
                if (ci + 3 < 24) {
                    loadB((ci + 3) & 3, ci + 3);
                    CP_COMMIT();
                }
                const uint32_t stB = sb + SMEM_A + (uint32_t)(ci & 3) * STAGE_B;
#pragma unroll
                for (int ks = 0; ks < 2; ks++) {
                    const uint32_t axk = (uint32_t)((c * 2 + ks) << 5);
                    const uint32_t bxk = (uint32_t)(ks << 5);
                    uint32_t af[2][4], bh[8][2];
#pragma unroll
                    for (int n2 = 0; n2 < 4; n2++) {
                        uint32_t a = stB + (bOff[n2] ^ bxk);
                        ldsm4(a, bh[2 * n2][0], bh[2 * n2][1],
                              bh[2 * n2 + 1][0], bh[2 * n2 + 1][1]);
                    }
                    ldsm4(sb + (aOff[0] ^ axk), af[0][0], af[0][1], af[0][2], af[0][3]);
                    ldsm4(sb + (aOff[1] ^ axk), af[1][0], af[1][1], af[1][2], af[1][3]);
#pragma unroll
                    for (int mt = 0; mt < 2; mt++)
#pragma unroll
                        for (int nt = 0; nt < 8; nt++) mma16816(acc[mt][nt], af[mt], bh[nt]);
                }
            }

            // ---- phase epilogue ----
            const float* bb = (ph == 0) ? b1 : (ph == 1) ? b2 : bp;
            float img = 1.0f;
            int coff = 0;
            float frv[8];
            if (ph == 1) {
                img = read_img(imgp);
                coff = wn >> 1;
#pragma unroll
                for (int nt = 0; nt < 8; nt++) {
                    int f = ((cl0 + nt * 8) & 127) >> 1;
                    frv[nt] = exp2f(-(float)f * 0.20762050593046015f);  // 10000^(-f/64)
                }
            }
            __syncthreads();   // all warps done reading A region for this phase

#pragma unroll
            for (int mt = 0; mt < 2; mt++) {
                int r0l = rl0 + mt * 16;
                int r1l = r0l + 8;
                float x0 = 0.0f, x1 = 0.0f;
                if (ph == 1) {
                    x0 = (verts[2 * (brow + r0l) + coff] / img) * 1000.0f;
                    x1 = (verts[2 * (brow + r1l) + coff] / img) * 1000.0f;
                }
#pragma unroll
                for (int nt = 0; nt < 8; nt++) {
                    int col = cl0 + nt * 8;
                    float b0 = __ldg(&bb[col]), b1v = __ldg(&bb[col + 1]);
                    float v00 = acc[mt][nt][0] + b0, v01 = acc[mt][nt][1] + b1v;
                    float v10 = acc[mt][nt][2] + b0, v11 = acc[mt][nt][3] + b1v;
                    if (ph == 0) {
                        v00 = fmaxf(v00, 0.0f); v01 = fmaxf(v01, 0.0f);
                        v10 = fmaxf(v10, 0.0f); v11 = fmaxf(v11, 0.0f);
                    }
                    if (ph == 1) {
                        float fr = frv[nt];
                        float a0 = x0 * fr, a1 = x1 * fr;
                        float k0 = rintf(a0 * 0.15915494309189535f);
                        float q0 = fmaf(-k0, 6.2831854820251465f, a0);
                        q0 = fmaf(-k0, -1.7484555e-07f, q0);
                        float k1 = rintf(a1 * 0.15915494309189535f);
                        float q1 = fmaf(-k1, 6.2831854820251465f, a1);
                        q1 = fmaf(-k1, -1.7484555e-07f, q1);
                        v00 += __sinf(q0); v01 += __cosf(q0);
                        v10 += __sinf(q1); v11 += __cosf(q1);
                    }
                    if (ph == 2) {
                        *(float2*)(OutF + (size_t)(brow + r0l) * DD + col) = make_float2(v00, v01);
                        *(float2*)(OutF + (size_t)(brow + r1l) * DD + col) = make_float2(v10, v11);
                    } else {
                        uint32_t u = (uint32_t)(col >> 3);
                        __half2 h0 = __floats2half2_rn(v00, v01);
                        __half2 h1 = __floats2half2_rn(v10, v11);
                        uint32_t lo4 = (uint32_t)(lane & 3) * 4;
                        sts32(sb + (uint32_t)(r0l << 9) + ((u ^ (uint32_t)(r0l & 7)) << 4) + lo4,
                              reinterpret_cast<uint32_t&>(h0));
                        sts32(sb + (uint32_t)(r1l << 9) + ((u ^ (uint32_t)(r1l & 7)) << 4) + lo4,
                              reinterpret_cast<uint32_t&>(h1));
                        acc[mt][nt][0] = 0.0f; acc[mt][nt][1] = 0.0f;
                        acc[mt][nt][2] = 0.0f; acc[mt][nt][3] = 0.0f;
                    }
                }
            }
            // next phase's top-of-loop __syncthreads orders these STS before ldsm
        }
        __syncthreads();   // A region quiesced before next tile's queue broadcast
    }
}

// ---------------------------------------------------------------------------
extern "C" void kernel_launch(void* const* d_in, const int* in_sizes, int n_in,
                              void* d_out, int out_size) {
    const float* features = (const float*)d_in[0];
    const float* vertices = (const float*)d_in[1];
    const int* imgp = (const int*)d_in[2];
    const float* W1 = (const float*)d_in[3];
    const float* b1 = (const float*)d_in[4];
    const float* W2 = (const float*)d_in[5];
    const float* b2 = (const float*)d_in[6];
    const float* Wp = (const float*)d_in[7];
    const float* bp = (const float*)d_in[8];
    float* out = (float*)d_out;

    void *pWh, *pFl;
    cudaGetSymbolAddress(&pWh, g_Wh);
    cudaGetSymbolAddress(&pFl, g_flags);
    __half* Wh = (__half*)pWh;

    cudaFuncSetAttribute(mega_kernel, cudaFuncAttributeMaxDynamicSharedMemorySize, GSMEM);

    int nsm = 148;
    cudaDeviceGetAttribute(&nsm, cudaDevAttrMultiProcessorCount, 0);
    int grid = 2 * nsm;   // all CTAs co-resident (occ-2) -> spin-safe

    cudaMemsetAsync(pFl, 0, sizeof(int) * 20);
    prep_weights<<<dim3(DD * CC / 256, 3), 256>>>(W1, W2, Wp);
    mega_kernel<<<grid, 256, GSMEM>>>(features, Wh, b1, b2, bp, out, vertices, imgp);
}

// round 14
// speedup vs baseline: 1.0826x; 1.0826x over previous
#include <cuda_runtime.h>
#include <cuda_fp16.h>
#include <cstdint>

#define BB 16
#define CC 256
#define HH 128
#define WW 128
#define NV 4096
#define DD 256
#define MROWS (BB * NV)   // 65536
#define HWSZ (HH * WW)    // 16384
#define NTILES (MROWS / 64)   // 1024

// ---------------- scratch (static __device__: allocation-free) ----------------
__device__ __half g_featT[(size_t)BB * HWSZ * CC];   // 128 MiB transposed features (B,HW,C) fp16
__device__ __half g_Wh[3][DD * CC];                  // weights [N,K] K-major, fp16
__device__ int g_flags[20];                          // [0..15]=batch strip counters, [16]=tile queue

__device__ __forceinline__ float read_img(const int* p) {
    int iv = *p;
    if (iv > 1 && iv < (1 << 24)) return (float)iv;
    return __int_as_float(iv);
}

// ---------------- family-agnostic PTX helpers (sm_80+) ----------------
__device__ __forceinline__ uint32_t smem_u32(const void* p) {
    uint32_t a;
    asm("{ .reg .u64 t; cvta.to.shared.u64 t, %1; cvt.u32.u64 %0, t; }" : "=r"(a) : "l"(p));
    return a;
}
__device__ __forceinline__ void cpa16(uint32_t dst, const void* src) {
    asm volatile("cp.async.cg.shared.global [%0], [%1], 16;" :: "r"(dst), "l"(src));
}
#define CP_COMMIT() asm volatile("cp.async.commit_group;" ::: "memory")
#define CP_WAIT2() asm volatile("cp.async.wait_group 2;" ::: "memory")
#define CP_WAIT1() asm volatile("cp.async.wait_group 1;" ::: "memory")
#define CP_WAIT0() asm volatile("cp.async.wait_group 0;" ::: "memory")

__device__ __forceinline__ void ldsm4(uint32_t a, uint32_t& r0, uint32_t& r1,
                                      uint32_t& r2, uint32_t& r3) {
    asm volatile("ldmatrix.sync.aligned.m8n8.x4.shared.b16 {%0,%1,%2,%3}, [%4];"
                 : "=r"(r0), "=r"(r1), "=r"(r2), "=r"(r3) : "r"(a));
}
__device__ __forceinline__ void mma16816(float* c, const uint32_t* a, const uint32_t* b) {
    asm volatile(
        "mma.sync.aligned.m16n8k16.row.col.f32.f16.f16.f32 "
        "{%0,%1,%2,%3}, {%4,%5,%6,%7}, {%8,%9}, {%0,%1,%2,%3};"
        : "+f"(c[0]), "+f"(c[1]), "+f"(c[2]), "+f"(c[3])
        : "r"(a[0]), "r"(a[1]), "r"(a[2]), "r"(a[3]), "r"(b[0]), "r"(b[1]));
}
__device__ __forceinline__ void sts32(uint32_t a, uint32_t v) {
    asm volatile("st.shared.b32 [%0], %1;" :: "r"(a), "r"(v));
}
__device__ __forceinline__ void sts128(uint32_t a, uint4 v) {
    asm volatile("st.shared.v4.b32 [%0], {%1,%2,%3,%4};"
                 :: "r"(a), "r"(v.x), "r"(v.y), "r"(v.z), "r"(v.w));
}

// ---------------------------------------------------------------------------
// K1: weight prep -> Wt[n*K+k] = W[k*Nd+n] as fp16
// ---------------------------------------------------------------------------
__global__ void prep_weights(const float* __restrict__ W1, const float* __restrict__ W2,
                             const float* __restrict__ Wp) {
    int idx = blockIdx.x * 256 + threadIdx.x;
    int w = blockIdx.y;
    const float* W = (w == 0) ? W1 : (w == 1) ? W2 : Wp;
    int n = idx >> 8, k = idx & 255;
    g_Wh[w][n * CC + k] = __float2half_rn(W[k * DD + n]);
}

// ---------------------------------------------------------------------------
// K2: PERSISTENT self-producing tile kernel.
//   grid = 2*SMs (all co-resident -> cross-CTA spin safe). Per tile i:
//   1) transpose hw-rows [(i&63)*256, +256) of batch i>>6 (its 1/64 share),
//      bump batch counter;  2) prefetch weights;  3) spin until batch's 64
//      shares done;  4) bilinear gather -> A smem;  5) fused 3-layer MLP.
//   Transpose (DRAM-bound) from late tiles overlaps MLP (tensor-bound) of
//   early tiles across the whole chip.
// ---------------------------------------------------------------------------
#define SMEM_A 32768
#define STAGE_B 16384
#define GSMEM (SMEM_A + 4 * STAGE_B)   // 98304 -> 2 CTAs/SM

__global__ void __launch_bounds__(256, 2)
mega_kernel(const float* __restrict__ features, const __half* __restrict__ Wh,
            const float* __restrict__ b1, const float* __restrict__ b2,
            const float* __restrict__ bp, float* __restrict__ OutF,
            const float* __restrict__ verts, const int* __restrict__ imgp) {
    extern __shared__ char smem[];
    const uint32_t sb = smem_u32(smem);
    const int tid = threadIdx.x;
    const int warp = tid >> 5, lane = tid & 31;
    const int wm = warp >> 2, wn = warp & 3;   // 2m x 4n warps -> 32x64 tiles

    // ---- weight chunk loader: ci 0..23 -> phase ci>>3, K32 chunk ci&7 ----
    auto loadB = [&](int s, int ci) {
        int ph = ci >> 3;
        uint32_t cofs = (uint32_t)(ci & 7) << 5;
        const __half* wh = Wh + (size_t)ph * DD * CC;
        uint32_t dstb = sb + SMEM_A + (uint32_t)s * STAGE_B;
#pragma unroll
        for (int i = 0; i < 4; i++) {
            int idx = i * 256 + tid;
            int rb = idx >> 2;
            uint32_t u = (uint32_t)(idx & 3);
            uint32_t sw = (uint32_t)(rb << 6) + ((u ^ (uint32_t)((rb >> 1) & 3)) << 4);
            cpa16(dstb + sw, wh + (size_t)rb * CC + cofs + u * 8);
        }
    };

    // ---- ldsm offsets (tile-independent) ----
    uint32_t aOff[2], bOff[4];
#pragma unroll
    for (int mt = 0; mt < 2; mt++) {
        int r = wm * 32 + mt * 16 + (lane & 15);
        uint32_t kb = (uint32_t)(lane >> 4);
        aOff[mt] = (uint32_t)(r << 9) + ((kb ^ (uint32_t)(r & 7)) << 4);
    }
#pragma unroll
    for (int n2 = 0; n2 < 4; n2++) {
        int rb = wn * 64 + n2 * 16 + (lane & 7) + ((lane >> 4) << 3);
        uint32_t kb = (uint32_t)((lane >> 3) & 1);
        bOff[n2] = (uint32_t)(rb << 6) + ((kb ^ (uint32_t)((rb >> 1) & 3)) << 4);
    }
    const int rl0 = wm * 32 + (lane >> 2);
    const int cl0 = wn * 64 + (lane & 3) * 2;

    while (true) {
        // pull next tile from the queue (block-wide broadcast via smem)
        if (tid == 0) *(volatile int*)smem = atomicAdd(&g_flags[16], 1);
        __syncthreads();
        const int tile = *(volatile int*)smem;
        __syncthreads();   // everyone read the broadcast before smem reuse
        if (tile >= NTILES) break;
        const int brow = tile * 64;
        const int batch = tile >> 6;

        // ---- STEP 1: transpose this tile's share of its batch ----
        // hw rows [(tile&63)*256, +256), all 256 channels -> g_featT
        {
            float* ft = (float*)smem;   // 4 staging tiles of 64x65 fp32 = 66560 B
            const float* s = features + (size_t)batch * CC * HWSZ;
            __half* d = g_featT + (size_t)batch * HWSZ * CC;
            const int hwbase = (tile & 63) * 256;
#pragma unroll
            for (int ss = 0; ss < 4; ss++) {
                int hw0 = hwbase + ss * 64;
#pragma unroll
                for (int t = 0; t < 4; t++)
#pragma unroll
                    for (int i = 0; i < 4; i++) {
                        int idx = tid + i * 256;
                        int r = idx >> 4, q = idx & 15;
                        float4 v = *(const float4*)(s + (size_t)(t * 64 + r) * HWSZ + hw0 + q * 4);
                        float* p = ft + t * 4160 + r * 65 + q * 4;
                        p[0] = v.x; p[1] = v.y; p[2] = v.z; p[3] = v.w;
                    }
                __syncthreads();
#pragma unroll
                for (int t = 0; t < 4; t++)
#pragma unroll
                    for (int i = 0; i < 2; i++) {
                        int idx = tid + i * 256;
                        int r = idx >> 3, q = idx & 7;
                        __half2 h[4];
#pragma unroll
                        for (int j = 0; j < 4; j++) {
                            float a = ft[t * 4160 + (q * 8 + 2 * j + 0) * 65 + r];
                            float c2 = ft[t * 4160 + (q * 8 + 2 * j + 1) * 65 + r];
                            h[j] = __floats2half2_rn(a, c2);
                        }
                        *(uint4*)(d + (size_t)(hw0 + r) * CC + t * 64 + q * 8) = *(uint4*)h;
                    }
                __syncthreads();
            }
            __threadfence();
            __syncthreads();
            if (tid == 0) atomicAdd(&g_flags[batch], 1);
        }

        float acc[2][8][4];
#pragma unroll
        for (int i = 0; i < 2; i++)
#pragma unroll
            for (int j = 0; j < 8; j++)
#pragma unroll
                for (int q = 0; q < 4; q++) acc[i][j][q] = 0.0f;

        // ---- STEP 2: prefetch weights (independent of feature readiness) ----
        loadB(0, 0);
        CP_COMMIT();
        loadB(1, 1);
        CP_COMMIT();
        loadB(2, 2);
        CP_COMMIT();

        // ---- STEP 3: spin until this batch's 64 transpose shares are done ----
        if (tid == 0) {
            while (atomicAdd(&g_flags[batch], 0) < 64) __nanosleep(100);
            __threadfence();
        }
        __syncthreads();

        // ---- STEP 4: bilinear gather -> A smem (warp = 8 vertices) ----
        {
            float img = read_img(imgp);
            float denom = img - 1.0f;
            const __half* fbase = g_featT + (size_t)batch * HWSZ * CC;
#pragma unroll
            for (int i = 0; i < 8; i++) {
                int rl = warp * 8 + i;
                int v = brow + rl;
                float gx = 2.0f * verts[2 * v + 0] / denom - 1.0f;
                float gy = 2.0f * verts[2 * v + 1] / denom - 1.0f;
                float ix = (gx + 1.0f) * 0.5f * (float)(WW - 1);
                float iy = (gy + 1.0f) * 0.5f * (float)(HH - 1);
                ix = fminf(fmaxf(ix, 0.0f), (float)(WW - 1));
                iy = fminf(fmaxf(iy, 0.0f), (float)(HH - 1));
                float x0f = floorf(ix), y0f = floorf(iy);
                float wx = ix - x0f, wy = iy - y0f;
                int x0 = min(max((int)x0f, 0), WW - 1);
                int y0 = min(max((int)y0f, 0), HH - 1);
                int x1 = min(x0 + 1, WW - 1);
                int y1 = min(y0 + 1, HH - 1);

                const __half* p00 = fbase + (size_t)(y0 * WW + x0) * CC + lane * 8;
                const __half* p01 = fbase + (size_t)(y0 * WW + x1) * CC + lane * 8;
                const __half* p10 = fbase + (size_t)(y1 * WW + x0) * CC + lane * 8;
                const __half* p11 = fbase + (size_t)(y1 * WW + x1) * CC + lane * 8;
                uint4 u00 = *(const uint4*)p00;
                uint4 u01 = *(const uint4*)p01;
                uint4 u10 = *(const uint4*)p10;
                uint4 u11 = *(const uint4*)p11;

                float omx = 1.0f - wx, omy = 1.0f - wy;
                float w00 = omx * omy, w01 = wx * omy, w10 = omx * wy, w11 = wx * wy;
                const uint32_t* a00 = (const uint32_t*)&u00;
                const uint32_t* a01 = (const uint32_t*)&u01;
                const uint32_t* a10 = (const uint32_t*)&u10;
                const uint32_t* a11 = (const uint32_t*)&u11;
                uint4 ov;
                uint32_t* op = (uint32_t*)&ov;
#pragma unroll
                for (int t = 0; t < 4; t++) {
                    float2 f00 = __half22float2(*(const __half2*)&a00[t]);
                    float2 f01 = __half22float2(*(const __half2*)&a01[t]);
                    float2 f10 = __half22float2(*(const __half2*)&a10[t]);
                    float2 f11 = __half22float2(*(const __half2*)&a11[t]);
                    float r0 = f00.x * w00 + f01.x * w01 + f10.x * w10 + f11.x * w11;
                    float r1 = f00.y * w00 + f01.y * w01 + f10.y * w10 + f11.y * w11;
                    __half2 h2 = __floats2half2_rn(r0, r1);
                    op[t] = reinterpret_cast<uint32_t&>(h2);
                }
                sts128(sb + (uint32_t)(rl << 9) + (((uint32_t)lane ^ (uint32_t)(rl & 7)) << 4), ov);
            }
        }

        // ---- STEP 5: fused 3-phase MLP ----
#pragma unroll
        for (int ph = 0; ph < 3; ph++) {
#pragma unroll
            for (int c = 0; c < 8; c++) {
                const int ci = ph * 8 + c;
                if (ci <= 21) CP_WAIT2();
                else if (ci == 22) CP_WAIT1();
                else CP_WAIT0();
                __syncthreads();
                if (ci + 3 < 24) {
                    loadB((ci + 3) & 3, ci + 3);
                    CP_COMMIT();
                }
                const uint32_t stB = sb + SMEM_A + (uint32_t)(ci & 3) * STAGE_B;
#pragma unroll
                for (int ks = 0; ks < 2; ks++) {
                    const uint32_t axk = (uint32_t)((c * 2 + ks) << 5);
                    const uint32_t bxk = (uint32_t)(ks << 5);
                    uint32_t af[2][4], bh[8][2];
#pragma unroll
                    for (int n2 = 0; n2 < 4; n2++) {
                        uint32_t a = stB + (bOff[n2] ^ bxk);
                        ldsm4(a, bh[2 * n2][0], bh[2 * n2][1],
                              bh[2 * n2 + 1][0], bh[2 * n2 + 1][1]);
                    }
                    ldsm4(sb + (aOff[0] ^ axk), af[0][0], af[0][1], af[0][2], af[0][3]);
                    ldsm4(sb + (aOff[1] ^ axk), af[1][0], af[1][1], af[1][2], af[1][3]);
#pragma unroll
                    for (int mt = 0; mt < 2; mt++)
#pragma unroll
                        for (int nt = 0; nt < 8; nt++) mma16816(acc[mt][nt], af[mt], bh[nt]);
                }
            }

            // ---- phase epilogue ----
            const float* bb = (ph == 0) ? b1 : (ph == 1) ? b2 : bp;
            float img = 1.0f;
            int coff = 0;
            float frv[8];
            if (ph == 1) {
                img = read_img(imgp);
                coff = wn >> 1;
#pragma unroll
                for (int nt = 0; nt < 8; nt++) {
                    int f = ((cl0 + nt * 8) & 127) >> 1;
                    frv[nt] = exp2f(-(float)f * 0.20762050593046015f);  // 10000^(-f/64)
                }
            }
            __syncthreads();   // all warps done reading A region for this phase

#pragma unroll
            for (int mt = 0; mt < 2; mt++) {
                int r0l = rl0 + mt * 16;
                int r1l = r0l + 8;
                float x0 = 0.0f, x1 = 0.0f;
                if (ph == 1) {
                    x0 = (verts[2 * (brow + r0l) + coff] / img) * 1000.0f;
                    x1 = (verts[2 * (brow + r1l) + coff] / img) * 1000.0f;
                }
#pragma unroll
                for (int nt = 0; nt < 8; nt++) {
                    int col = cl0 + nt * 8;
                    float b0 = __ldg(&bb[col]), b1v = __ldg(&bb[col + 1]);
                    float v00 = acc[mt][nt][0] + b0, v01 = acc[mt][nt][1] + b1v;
                    float v10 = acc[mt][nt][2] + b0, v11 = acc[mt][nt][3] + b1v;
                    if (ph == 0) {
                        v00 = fmaxf(v00, 0.0f); v01 = fmaxf(v01, 0.0f);
                        v10 = fmaxf(v10, 0.0f); v11 = fmaxf(v11, 0.0f);
                    }
                    if (ph == 1) {
                        float fr = frv[nt];
                        float a0 = x0 * fr, a1 = x1 * fr;
                        float k0 = rintf(a0 * 0.15915494309189535f);
                        float q0 = fmaf(-k0, 6.2831854820251465f, a0);
                        q0 = fmaf(-k0, -1.7484555e-07f, q0);
                        float k1 = rintf(a1 * 0.15915494309189535f);
                        float q1 = fmaf(-k1, 6.2831854820251465f, a1);
                        q1 = fmaf(-k1, -1.7484555e-07f, q1);
                        v00 += __sinf(q0); v01 += __cosf(q0);
                        v10 += __sinf(q1); v11 += __cosf(q1);
                    }
                    if (ph == 2) {
                        *(float2*)(OutF + (size_t)(brow + r0l) * DD + col) = make_float2(v00, v01);
                        *(float2*)(OutF + (size_t)(brow + r1l) * DD + col) = make_float2(v10, v11);
                    } else {
                        uint32_t u = (uint32_t)(col >> 3);
                        __half2 h0 = __floats2half2_rn(v00, v01);
                        __half2 h1 = __floats2half2_rn(v10, v11);
                        uint32_t lo4 = (uint32_t)(lane & 3) * 4;
                        sts32(sb + (uint32_t)(r0l << 9) + ((u ^ (uint32_t)(r0l & 7)) << 4) + lo4,
                              reinterpret_cast<uint32_t&>(h0));
                        sts32(sb + (uint32_t)(r1l << 9) + ((u ^ (uint32_t)(r1l & 7)) << 4) + lo4,
                              reinterpret_cast<uint32_t&>(h1));
                        acc[mt][nt][0] = 0.0f; acc[mt][nt][1] = 0.0f;
                        acc[mt][nt][2] = 0.0f; acc[mt][nt][3] = 0.0f;
                    }
                }
            }
            // next phase's top-of-loop __syncthreads orders these STS before ldsm
        }
        __syncthreads();   // A region quiesced before next tile's queue broadcast
    }
}

// ---------------------------------------------------------------------------
extern "C" void kernel_launch(void* const* d_in, const int* in_sizes, int n_in,
                              void* d_out, int out_size) {
    const float* features = (const float*)d_in[0];
    const float* vertices = (const float*)d_in[1];
    const int* imgp = (const int*)d_in[2];
    const float* W1 = (const float*)d_in[3];
    const float* b1 = (const float*)d_in[4];
    const float* W2 = (const float*)d_in[5];
    const float* b2 = (const float*)d_in[6];
    const float* Wp = (const float*)d_in[7];
    const float* bp = (const float*)d_in[8];
    float* out = (float*)d_out;

    void *pWh, *pFl;
    cudaGetSymbolAddress(&pWh, g_Wh);
    cudaGetSymbolAddress(&pFl, g_flags);
    __half* Wh = (__half*)pWh;

    cudaFuncSetAttribute(mega_kernel, cudaFuncAttributeMaxDynamicSharedMemorySize, GSMEM);

    int nsm = 148;
    cudaDeviceGetAttribute(&nsm, cudaDevAttrMultiProcessorCount, 0);
    int grid = 2 * nsm;   // all CTAs co-resident (occ-2) -> spin-safe

    cudaMemsetAsync(pFl, 0, sizeof(int) * 20);
    prep_weights<<<dim3(DD * CC / 256, 3), 256>>>(W1, W2, Wp);
    mega_kernel<<<grid, 256, GSMEM>>>(features, Wh, b1, b2, bp, out, vertices, imgp);
}

// round 15
// speedup vs baseline: 1.2265x; 1.1329x over previous
#include <cuda_runtime.h>
#include <cuda_fp16.h>
#include <cstdint>

#define BB 16
#define CC 256
#define HH 128
#define WW 128
#define NV 4096
#define DD 256
#define MROWS (BB * NV)   // 65536
#define HWSZ (HH * WW)    // 16384

// ---------------- scratch (static __device__: allocation-free) ----------------
__device__ __half g_featT[(size_t)BB * HWSZ * CC];   // 128 MiB transposed features (B,HW,C) fp16
__device__ __half g_Wh[3][DD * CC];                  // weights [N,K] K-major, fp16

__device__ __forceinline__ float read_img(const int* p) {
    int iv = *p;
    if (iv > 1 && iv < (1 << 24)) return (float)iv;
    return __int_as_float(iv);
}

// ---------------- family-agnostic PTX helpers (sm_80+) ----------------
__device__ __forceinline__ uint32_t smem_u32(const void* p) {
    uint32_t a;
    asm("{ .reg .u64 t; cvta.to.shared.u64 t, %1; cvt.u32.u64 %0, t; }" : "=r"(a) : "l"(p));
    return a;
}
__device__ __forceinline__ void cpa16(uint32_t dst, const void* src) {
    asm volatile("cp.async.cg.shared.global [%0], [%1], 16;" :: "r"(dst), "l"(src));
}
#define CP_COMMIT() asm volatile("cp.async.commit_group;" ::: "memory")
#define CP_WAIT2() asm volatile("cp.async.wait_group 2;" ::: "memory")
#define CP_WAIT1() asm volatile("cp.async.wait_group 1;" ::: "memory")
#define CP_WAIT0() asm volatile("cp.async.wait_group 0;" ::: "memory")

__device__ __forceinline__ void ldsm4(uint32_t a, uint32_t& r0, uint32_t& r1,
                                      uint32_t& r2, uint32_t& r3) {
    asm volatile("ldmatrix.sync.aligned.m8n8.x4.shared.b16 {%0,%1,%2,%3}, [%4];"
                 : "=r"(r0), "=r"(r1), "=r"(r2), "=r"(r3) : "r"(a));
}
__device__ __forceinline__ void mma16816(float* c, const uint32_t* a, const uint32_t* b) {
    asm volatile(
        "mma.sync.aligned.m16n8k16.row.col.f32.f16.f16.f32 "
        "{%0,%1,%2,%3}, {%4,%5,%6,%7}, {%8,%9}, {%0,%1,%2,%3};"
        : "+f"(c[0]), "+f"(c[1]), "+f"(c[2]), "+f"(c[3])
        : "r"(a[0]), "r"(a[1]), "r"(a[2]), "r"(a[3]), "r"(b[0]), "r"(b[1]));
}
__device__ __forceinline__ void sts32(uint32_t a, uint32_t v) {
    asm volatile("st.shared.b32 [%0], %1;" :: "r"(a), "r"(v));
}
__device__ __forceinline__ void sts128(uint32_t a, uint4 v) {
    asm volatile("st.shared.v4.b32 [%0], {%1,%2,%3,%4};"
                 :: "r"(a), "r"(v.x), "r"(v.y), "r"(v.z), "r"(v.w));
}

// ---------------------------------------------------------------------------
// K1: transpose (B,C,H,W) fp32 -> (B,HW,C) fp16, with weight prep folded in.
//   CTAs with (y==0 && z==0) additionally convert a 768-element weight slice
//   (hidden inside the 57us DRAM-bound kernel; removes the serial prep launch).
// ---------------------------------------------------------------------------
__global__ void __launch_bounds__(256) transpose_kernel(
    const float* __restrict__ src, const float* __restrict__ W1,
    const float* __restrict__ W2, const float* __restrict__ Wp) {
    __shared__ float sm[64 * 65];
    int b = blockIdx.z;
    int hw0 = blockIdx.x * 64;
    int c0 = blockIdx.y * 64;
    int tid = threadIdx.x;

    // folded weight prep: 256 CTAs x 768 elems = 196608 = 3 * 256 * 256
    if (blockIdx.y == 0 && blockIdx.z == 0) {
#pragma unroll
        for (int i = 0; i < 3; i++) {
            int gi = (blockIdx.x * 3 + i) * 256 + tid;   // 0 .. 196607
            int w = gi >> 16;                             // matrix 0..2
            int idx = gi & 65535;
            int n = idx >> 8, k = idx & 255;
            const float* W = (w == 0) ? W1 : (w == 1) ? W2 : Wp;
            g_Wh[w][n * CC + k] = __float2half_rn(W[k * DD + n]);
        }
    }

    const float* s = src + (size_t)b * CC * HWSZ;
    __half* d = g_featT + (size_t)b * HWSZ * CC;
#pragma unroll
    for (int i = 0; i < 4; i++) {
        int idx = tid + i * 256;
        int r = idx >> 4, q = idx & 15;
        float4 v = *(const float4*)(s + (size_t)(c0 + r) * HWSZ + hw0 + q * 4);
        float* p = &sm[r * 65 + q * 4];
        p[0] = v.x; p[1] = v.y; p[2] = v.z; p[3] = v.w;
    }
    __syncthreads();
#pragma unroll
    for (int i = 0; i < 2; i++) {
        int idx = tid + i * 256;
        int r = idx >> 3, q = idx & 7;
        __half2 h[4];
#pragma unroll
        for (int j = 0; j < 4; j++) {
            float a = sm[(q * 8 + 2 * j + 0) * 65 + r];
            float bb2 = sm[(q * 8 + 2 * j + 1) * 65 + r];
            h[j] = __floats2half2_rn(a, bb2);
        }
        *(uint4*)(d + (size_t)(hw0 + r) * CC + c0 + q * 8) = *(uint4*)h;
    }
}

// ---------------------------------------------------------------------------
// K2: FUSED gather + 3-layer MLP — occ-2 design (R12 structure, measured best).
//   256 threads / 8 warps, warp tile 32x64, CTA tile 64x256, grid 1024.
//   A (64 rows x 512B = 32KB) resident & recycled between phases.
//   Weights: 24 K32 chunks (8/phase), 4 x 16KB buffers, prefetch depth 3.
// ---------------------------------------------------------------------------
#define SMEM_A 32768
#define STAGE_B 16384
#define GSMEM (SMEM_A + 4 * STAGE_B)   // 98304 -> 2 CTAs/SM = 192KB

__global__ void __launch_bounds__(256, 2)
fused_mlp(const __half* __restrict__ Wh,
          const float* __restrict__ b1, const float* __restrict__ b2,
          const float* __restrict__ bp, float* __restrict__ OutF,
          const float* __restrict__ verts, const int* __restrict__ imgp) {
    extern __shared__ char smem[];
    const uint32_t sb = smem_u32(smem);
    const int tid = threadIdx.x;
    const int brow = blockIdx.x * 64;
    const int warp = tid >> 5, lane = tid & 31;
    const int wm = warp >> 2, wn = warp & 3;   // 2m x 4n warps -> 32x64 tiles

    float acc[2][8][4];
#pragma unroll
    for (int i = 0; i < 2; i++)
#pragma unroll
        for (int j = 0; j < 8; j++)
#pragma unroll
            for (int q = 0; q < 4; q++) acc[i][j][q] = 0.0f;

    // ---- weight chunk loader: ci 0..23 -> phase ci>>3, K32 chunk ci&7 ----
    auto loadB = [&](int s, int ci) {
        int ph = ci >> 3;
        uint32_t cofs = (uint32_t)(ci & 7) << 5;
        const __half* wh = Wh + (size_t)ph * DD * CC;
        uint32_t dstb = sb + SMEM_A + (uint32_t)s * STAGE_B;
#pragma unroll
        for (int i = 0; i < 4; i++) {
            int idx = i * 256 + tid;
            int rb = idx >> 2;
            uint32_t u = (uint32_t)(idx & 3);
            uint32_t sw = (uint32_t)(rb << 6) + ((u ^ (uint32_t)((rb >> 1) & 3)) << 4);
            cpa16(dstb + sw, wh + (size_t)rb * CC + cofs + u * 8);
        }
    };

    // prefetch weights first so the gather LDGs below overlap with them
    loadB(0, 0);
    CP_COMMIT();
    loadB(1, 1);
    CP_COMMIT();
    loadB(2, 2);
    CP_COMMIT();

    // ---- PROLOGUE: bilinear gather -> A smem (warp = 8 vertices) ----
    {
        const int b = brow >> 12;   // whole CTA is one batch (64 | 4096)
        float img = read_img(imgp);
        float denom = img - 1.0f;
        const __half* fbase = g_featT + (size_t)b * HWSZ * CC;
#pragma unroll
        for (int i = 0; i < 8; i++) {
            int rl = warp * 8 + i;          // local row 0..63
            int v = brow + rl;
            float gx = 2.0f * verts[2 * v + 0] / denom - 1.0f;
            float gy = 2.0f * verts[2 * v + 1] / denom - 1.0f;
            float ix = (gx + 1.0f) * 0.5f * (float)(WW - 1);
            float iy = (gy + 1.0f) * 0.5f * (float)(HH - 1);
            ix = fminf(fmaxf(ix, 0.0f), (float)(WW - 1));
            iy = fminf(fmaxf(iy, 0.0f), (float)(HH - 1));
            float x0f = floorf(ix), y0f = floorf(iy);
            float wx = ix - x0f, wy = iy - y0f;
            int x0 = min(max((int)x0f, 0), WW - 1);
            int y0 = min(max((int)y0f, 0), HH - 1);
            int x1 = min(x0 + 1, WW - 1);
            int y1 = min(y0 + 1, HH - 1);

            const __half* p00 = fbase + (size_t)(y0 * WW + x0) * CC + lane * 8;
            const __half* p01 = fbase + (size_t)(y0 * WW + x1) * CC + lane * 8;
            const __half* p10 = fbase + (size_t)(y1 * WW + x0) * CC + lane * 8;
            const __half* p11 = fbase + (size_t)(y1 * WW + x1) * CC + lane * 8;
            uint4 u00 = *(const uint4*)p00;
            uint4 u01 = *(const uint4*)p01;
            uint4 u10 = *(const uint4*)p10;
            uint4 u11 = *(const uint4*)p11;

            float omx = 1.0f - wx, omy = 1.0f - wy;
            float w00 = omx * omy, w01 = wx * omy, w10 = omx * wy, w11 = wx * wy;
            const uint32_t* a00 = (const uint32_t*)&u00;
            const uint32_t* a01 = (const uint32_t*)&u01;
            const uint32_t* a10 = (const uint32_t*)&u10;
            const uint32_t* a11 = (const uint32_t*)&u11;
            uint4 ov;
            uint32_t* op = (uint32_t*)&ov;
#pragma unroll
            for (int t = 0; t < 4; t++) {
                float2 f00 = __half22float2(*(const __half2*)&a00[t]);
                float2 f01 = __half22float2(*(const __half2*)&a01[t]);
                float2 f10 = __half22float2(*(const __half2*)&a10[t]);
                float2 f11 = __half22float2(*(const __half2*)&a11[t]);
                float r0 = f00.x * w00 + f01.x * w01 + f10.x * w10 + f11.x * w11;
                float r1 = f00.y * w00 + f01.y * w01 + f10.y * w10 + f11.y * w11;
                __half2 h2 = __floats2half2_rn(r0, r1);
                op[t] = reinterpret_cast<uint32_t&>(h2);
            }
            // A smem: row rl, 16B-unit = lane, unit ^= (rl&7)
            sts128(sb + (uint32_t)(rl << 9) + (((uint32_t)lane ^ (uint32_t)(rl & 7)) << 4), ov);
        }
    }

    // ---- ldsm offsets ----
    uint32_t aOff[2], bOff[4];
#pragma unroll
    for (int mt = 0; mt < 2; mt++) {
        int r = wm * 32 + mt * 16 + (lane & 15);
        uint32_t kb = (uint32_t)(lane >> 4);
        aOff[mt] = (uint32_t)(r << 9) + ((kb ^ (uint32_t)(r & 7)) << 4);
    }
#pragma unroll
    for (int n2 = 0; n2 < 4; n2++) {
        int rb = wn * 64 + n2 * 16 + (lane & 7) + ((lane >> 4) << 3);
        uint32_t kb = (uint32_t)((lane >> 3) & 1);
        bOff[n2] = (uint32_t)(rb << 6) + ((kb ^ (uint32_t)((rb >> 1) & 3)) << 4);
    }

    const int rl0 = wm * 32 + (lane >> 2);   // local row base
    const int cl0 = wn * 64 + (lane & 3) * 2;

#pragma unroll
    for (int ph = 0; ph < 3; ph++) {
#pragma unroll
        for (int c = 0; c < 8; c++) {
            const int ci = ph * 8 + c;
            if (ci <= 21) CP_WAIT2();
            else if (ci == 22) CP_WAIT1();
            else CP_WAIT0();
            __syncthreads();   // weights ready; A-region STS ordered
            if (ci + 3 < 24) {
                loadB((ci + 3) & 3, ci + 3);
                CP_COMMIT();
            }
            const uint32_t stB = sb + SMEM_A + (uint32_t)(ci & 3) * STAGE_B;
#pragma unroll
            for (int ks = 0; ks < 2; ks++) {
                const uint32_t axk = (uint32_t)((c * 2 + ks) << 5);
                const uint32_t bxk = (uint32_t)(ks << 5);
                uint32_t af[2][4], bh[8][2];
#pragma unroll
                for (int n2 = 0; n2 < 4; n2++) {
                    uint32_t a = stB + (bOff[n2] ^ bxk);
                    ldsm4(a, bh[2 * n2][0], bh[2 * n2][1],
                          bh[2 * n2 + 1][0], bh[2 * n2 + 1][1]);
                }
                ldsm4(sb + (aOff[0] ^ axk), af[0][0], af[0][1], af[0][2], af[0][3]);
                ldsm4(sb + (aOff[1] ^ axk), af[1][0], af[1][1], af[1][2], af[1][3]);
#pragma unroll
                for (int mt = 0; mt < 2; mt++)
#pragma unroll
                    for (int nt = 0; nt < 8; nt++) mma16816(acc[mt][nt], af[mt], bh[nt]);
            }
        }

        // ---- phase epilogue ----
        const float* bb = (ph == 0) ? b1 : (ph == 1) ? b2 : bp;
        float img = 1.0f;
        int coff = 0;
        float frv[8];
        if (ph == 1) {
            img = read_img(imgp);
            coff = wn >> 1;  // wn 0,1 -> x (cols 0-127); wn 2,3 -> y
#pragma unroll
            for (int nt = 0; nt < 8; nt++) {
                int f = ((cl0 + nt * 8) & 127) >> 1;
                frv[nt] = exp2f(-(float)f * 0.20762050593046015f);  // 10000^(-f/64)
            }
        }
        __syncthreads();   // all warps done reading A region for this phase

#pragma unroll
        for (int mt = 0; mt < 2; mt++) {
            int r0l = rl0 + mt * 16;
            int r1l = r0l + 8;
            float x0 = 0.0f, x1 = 0.0f;
            if (ph == 1) {
                x0 = (verts[2 * (brow + r0l) + coff] / img) * 1000.0f;
                x1 = (verts[2 * (brow + r1l) + coff] / img) * 1000.0f;
            }
#pragma unroll
            for (int nt = 0; nt < 8; nt++) {
                int col = cl0 + nt * 8;
                float b0 = __ldg(&bb[col]), b1v = __ldg(&bb[col + 1]);
                float v00 = acc[mt][nt][0] + b0, v01 = acc[mt][nt][1] + b1v;
                float v10 = acc[mt][nt][2] + b0, v11 = acc[mt][nt][3] + b1v;
                if (ph == 0) {
                    v00 = fmaxf(v00, 0.0f); v01 = fmaxf(v01, 0.0f);
                    v10 = fmaxf(v10, 0.0f); v11 = fmaxf(v11, 0.0f);
                }
                if (ph == 1) {
                    float fr = frv[nt];
                    float a0 = x0 * fr, a1 = x1 * fr;
                    float k0 = rintf(a0 * 0.15915494309189535f);
                    float q0 = fmaf(-k0, 6.2831854820251465f, a0);
                    q0 = fmaf(-k0, -1.7484555e-07f, q0);
                    float k1 = rintf(a1 * 0.15915494309189535f);
                    float q1 = fmaf(-k1, 6.2831854820251465f, a1);
                    q1 = fmaf(-k1, -1.7484555e-07f, q1);
                    v00 += __sinf(q0); v01 += __cosf(q0);
                    v10 += __sinf(q1); v11 += __cosf(q1);
                }
                if (ph == 2) {
                    *(float2*)(OutF + (size_t)(brow + r0l) * DD + col) = make_float2(v00, v01);
                    *(float2*)(OutF + (size_t)(brow + r1l) * DD + col) = make_float2(v10, v11);
                } else {
                    uint32_t u = (uint32_t)(col >> 3);
                    __half2 h0 = __floats2half2_rn(v00, v01);
                    __half2 h1 = __floats2half2_rn(v10, v11);
                    uint32_t lo4 = (uint32_t)(lane & 3) * 4;
                    sts32(sb + (uint32_t)(r0l << 9) + ((u ^ (uint32_t)(r0l & 7)) << 4) + lo4,
                          reinterpret_cast<uint32_t&>(h0));
                    sts32(sb + (uint32_t)(r1l << 9) + ((u ^ (uint32_t)(r1l & 7)) << 4) + lo4,
                          reinterpret_cast<uint32_t&>(h1));
                    acc[mt][nt][0] = 0.0f; acc[mt][nt][1] = 0.0f;
                    acc[mt][nt][2] = 0.0f; acc[mt][nt][3] = 0.0f;
                }
            }
        }
        // next phase's top-of-loop __syncthreads orders these STS before ldsm
    }
}

// ---------------------------------------------------------------------------
extern "C" void kernel_launch(void* const* d_in, const int* in_sizes, int n_in,
                              void* d_out, int out_size) {
    const float* features = (const float*)d_in[0];
    const float* vertices = (const float*)d_in[1];
    const int* imgp = (const int*)d_in[2];
    const float* W1 = (const float*)d_in[3];
    const float* b1 = (const float*)d_in[4];
    const float* W2 = (const float*)d_in[5];
    const float* b2 = (const float*)d_in[6];
    const float* Wp = (const float*)d_in[7];
    const float* bp = (const float*)d_in[8];
    float* out = (float*)d_out;

    void* pWh;
    cudaGetSymbolAddress(&pWh, g_Wh);
    __half* Wh = (__half*)pWh;

    cudaFuncSetAttribute(fused_mlp, cudaFuncAttributeMaxDynamicSharedMemorySize, GSMEM);

    transpose_kernel<<<dim3(HWSZ / 64, CC / 64, BB), 256>>>(features, W1, W2, Wp);
    fused_mlp<<<MROWS / 64, 256, GSMEM>>>(Wh, b1, b2, bp, out, vertices, imgp);
}